// round 13
// baseline (speedup 1.0000x reference)
#include <cuda_runtime.h>
#include <math_constants.h>

#define NB_B 32
#define NB_H 32
#define HKV 8
#define GQ 4
#define HD 128
#define BSZ 128
#define NBLK 16
#define TBLK (NB_B * NBLK)   // 512

__device__ float g_l[TBLK * HKV * GQ];
__device__ float g_o[TBLK * HKV * GQ * HD];

typedef unsigned long long u64;

__device__ __forceinline__ u64 pack2(float x, float y) {
    u64 r; asm("mov.b64 %0, {%1,%2};" : "=l"(r) : "f"(x), "f"(y)); return r;
}
__device__ __forceinline__ void unpack2(u64 v, float& x, float& y) {
    asm("mov.b64 {%0,%1}, %2;" : "=f"(x), "=f"(y) : "l"(v));
}
__device__ __forceinline__ u64 dup2(float x) {
    u64 r; asm("mov.b64 %0, {%1,%1};" : "=l"(r) : "f"(x)); return r;
}
__device__ __forceinline__ u64 fma2(u64 a, u64 b, u64 c) {
    u64 d; asm("fma.rn.f32x2 %0, %1, %2, %3;" : "=l"(d) : "l"(a), "l"(b), "l"(c)); return d;
}
__device__ __forceinline__ float dot4(float4 a, float4 b) {
    return fmaf(a.x, b.x, fmaf(a.y, b.y, fmaf(a.z, b.z, a.w * b.w)));
}

struct KV2 { float4 k0, v0, k1, v1; };

// Branch-free pair load straight from cache (new-token handled post-loop).
__device__ __forceinline__ KV2 load_pair(
    int s0, int nvalid, int lane, size_t rowstr,
    const float4* __restrict__ kbase, const float4* __restrict__ vbase)
{
    KV2 r;
    r.k0 = __ldcs(&kbase[(size_t)s0 * rowstr + lane]);
    r.v0 = __ldcs(&vbase[(size_t)s0 * rowstr + lane]);
    if (s0 + 1 < nvalid) {
        r.k1 = __ldcs(&kbase[(size_t)(s0 + 1) * rowstr + lane]);
        r.v1 = __ldcs(&vbase[(size_t)(s0 + 1) * rowstr + lane]);
    } else {
        r.k1 = make_float4(0.f, 0.f, 0.f, 0.f);
        r.v1 = make_float4(0.f, 0.f, 0.f, 0.f);
    }
    return r;
}

// One CTA per mapped block t; warp w owns kv head w. Software-pipelined.
__global__ void __launch_bounds__(256, 3)
attn_fused_kernel(const float* __restrict__ query,
                  const float* __restrict__ knew,
                  const float* __restrict__ vnew,
                  const float* __restrict__ kcache,
                  const float* __restrict__ vcache,
                  const int*   __restrict__ block_list,
                  const int*   __restrict__ block_groups,
                  const int*   __restrict__ block_indices,
                  const int*   __restrict__ block_offsets,
                  const float* __restrict__ bias)
{
    const int t    = blockIdx.x;
    const int tid  = threadIdx.x;
    const int lane = tid & 31;
    const int w    = tid >> 5;     // kv head

    __shared__ int s_sub;

    // Dead block: zero l (dead g_o entries are never read with nonzero weight).
    if (bias[t * BSZ] == -CUDART_INF_F) {
        if (tid < HKV * GQ) g_l[t * HKV * GQ + tid] = 0.0f;
        return;
    }

    const int grp = block_groups[t];
    const int cb  = block_list[t];

    if (tid == 0) {
        int sub = -1;
        #pragma unroll
        for (int b = 0; b < NB_B; b++) {
            if (block_indices[b] == cb) { sub = block_offsets[b] | (b << 16); break; }
        }
        s_sub = sub;
    }

    const int nvalid = __syncthreads_count(
        (tid < BSZ) && (bias[t * BSZ + tid] > -CUDART_INF_F));

    const int sub   = s_sub;
    const int sub_s = (sub < 0) ? -1 : (sub & 0xFFFF);
    const int sub_b = (sub < 0) ? 0  : (sub >> 16);

    const float SCL2 = 0.08838834764831845f * 1.4426950408889634f; // scale*log2e
    const float4* q4 = (const float4*)(query + ((size_t)grp * NB_H + w * GQ) * HD);
    float4 ql[GQ];
    #pragma unroll
    for (int g = 0; g < GQ; g++) {
        float4 qv = q4[g * (HD / 4) + lane];
        ql[g] = make_float4(qv.x * SCL2, qv.y * SCL2, qv.z * SCL2, qv.w * SCL2);
    }

    const size_t rowstr = (size_t)HKV * HD / 4;
    const float4* kbase = (const float4*)(kcache + ((size_t)cb * BSZ * HKV + w) * HD);
    const float4* vbase = (const float4*)(vcache + ((size_t)cb * BSZ * HKV + w) * HD);

    u64 aLo[GQ] = {0, 0, 0, 0}, aHi[GQ] = {0, 0, 0, 0};
    float lsum = 0.0f;
    const bool row_r = (lane & 16) != 0;
    const bool lo16  = !row_r;
    const bool hi8   = (lane & 8) != 0;
    const bool hi4   = (lane & 4) != 0;

    KV2 cur = load_pair(0, nvalid, lane, rowstr, kbase, vbase);

    for (int s0 = 0; s0 < nvalid; s0 += 2) {
        KV2 nxt;
        const int sn = s0 + 2;
        if (sn < nvalid)
            nxt = load_pair(sn, nvalid, lane, rowstr, kbase, vbase);

        const bool h1 = (s0 + 1 < nvalid);

        float v_[GQ], u_[GQ];
        #pragma unroll
        for (int g = 0; g < GQ; g++) {
            v_[g] = dot4(ql[g], cur.k0);
            u_[g] = dot4(ql[g], cur.k1);
        }

        float A[GQ];
        #pragma unroll
        for (int i = 0; i < GQ; i++) {
            float x  = lo16 ? u_[i] : v_[i];
            float rx = __shfl_xor_sync(0xFFFFFFFFu, x, 16);
            A[i] = (lo16 ? v_[i] : u_[i]) + rx;
        }
        float x0 = hi8 ? A[0] : A[2];
        float x1 = hi8 ? A[1] : A[3];
        float r0 = __shfl_xor_sync(0xFFFFFFFFu, x0, 8);
        float r1 = __shfl_xor_sync(0xFFFFFFFFu, x1, 8);
        float B0 = (hi8 ? A[2] : A[0]) + r0;
        float B1 = (hi8 ? A[3] : A[1]) + r1;
        float x2 = hi4 ? B0 : B1;
        float r2 = __shfl_xor_sync(0xFFFFFFFFu, x2, 4);
        float C  = (hi4 ? B1 : B0) + r2;
        C += __shfl_xor_sync(0xFFFFFFFFu, C, 2);
        C += __shfl_xor_sync(0xFFFFFFFFu, C, 1);
        if (row_r && !h1) C = -CUDART_INF_F;
        const float p = exp2f(C);
        lsum += p;

        const float p00 = __shfl_sync(0xFFFFFFFFu, p, 0);
        const float p01 = __shfl_sync(0xFFFFFFFFu, p, 4);
        const float p02 = __shfl_sync(0xFFFFFFFFu, p, 8);
        const float p03 = __shfl_sync(0xFFFFFFFFu, p, 12);
        const float p10 = __shfl_sync(0xFFFFFFFFu, p, 16);
        const float p11 = __shfl_sync(0xFFFFFFFFu, p, 20);
        const float p12 = __shfl_sync(0xFFFFFFFFu, p, 24);
        const float p13 = __shfl_sync(0xFFFFFFFFu, p, 28);

        const u64 vlo0 = pack2(cur.v0.x, cur.v0.y), vhi0 = pack2(cur.v0.z, cur.v0.w);
        const u64 vlo1 = pack2(cur.v1.x, cur.v1.y), vhi1 = pack2(cur.v1.z, cur.v1.w);

        aLo[0] = fma2(dup2(p00), vlo0, fma2(dup2(p10), vlo1, aLo[0]));
        aHi[0] = fma2(dup2(p00), vhi0, fma2(dup2(p10), vhi1, aHi[0]));
        aLo[1] = fma2(dup2(p01), vlo0, fma2(dup2(p11), vlo1, aLo[1]));
        aHi[1] = fma2(dup2(p01), vhi0, fma2(dup2(p11), vhi1, aHi[1]));
        aLo[2] = fma2(dup2(p02), vlo0, fma2(dup2(p12), vlo1, aLo[2]));
        aHi[2] = fma2(dup2(p02), vhi0, fma2(dup2(p12), vhi1, aHi[2]));
        aLo[3] = fma2(dup2(p03), vlo0, fma2(dup2(p13), vlo1, aLo[3]));
        aHi[3] = fma2(dup2(p03), vhi0, fma2(dup2(p13), vhi1, aHi[3]));

        cur = nxt;
    }

    // ---- new-token correction: subtract stale cache row, add new row ----
    if (sub_s >= 0) {
        const float4 kc = kbase[(size_t)sub_s * rowstr + lane];  // L1/L2 hot
        const float4 vc = vbase[(size_t)sub_s * rowstr + lane];
        const float4 kn = ((const float4*)(knew + ((size_t)sub_b * HKV + w) * HD))[lane];
        const float4 vn = ((const float4*)(vnew + ((size_t)sub_b * HKV + w) * HD))[lane];

        // fold with "row0 = stale cache row", "row1 = new row"
        float v_[GQ], u_[GQ];
        #pragma unroll
        for (int g = 0; g < GQ; g++) {
            v_[g] = dot4(ql[g], kc);
            u_[g] = dot4(ql[g], kn);
        }
        float A[GQ];
        #pragma unroll
        for (int i = 0; i < GQ; i++) {
            float x  = lo16 ? u_[i] : v_[i];
            float rx = __shfl_xor_sync(0xFFFFFFFFu, x, 16);
            A[i] = (lo16 ? v_[i] : u_[i]) + rx;
        }
        float x0 = hi8 ? A[0] : A[2];
        float x1 = hi8 ? A[1] : A[3];
        float r0 = __shfl_xor_sync(0xFFFFFFFFu, x0, 8);
        float r1 = __shfl_xor_sync(0xFFFFFFFFu, x1, 8);
        float B0 = (hi8 ? A[2] : A[0]) + r0;
        float B1 = (hi8 ? A[3] : A[1]) + r1;
        float x2 = hi4 ? B0 : B1;
        float r2 = __shfl_xor_sync(0xFFFFFFFFu, x2, 4);
        float C  = (hi4 ? B1 : B0) + r2;
        C += __shfl_xor_sync(0xFFFFFFFFu, C, 2);
        C += __shfl_xor_sync(0xFFFFFFFFu, C, 1);
        const float p = exp2f(C);
        lsum += row_r ? p : -p;   // + new, - stale

        const float pc0 = __shfl_sync(0xFFFFFFFFu, p, 0);
        const float pc1 = __shfl_sync(0xFFFFFFFFu, p, 4);
        const float pc2 = __shfl_sync(0xFFFFFFFFu, p, 8);
        const float pc3 = __shfl_sync(0xFFFFFFFFu, p, 12);
        const float pn0 = __shfl_sync(0xFFFFFFFFu, p, 16);
        const float pn1 = __shfl_sync(0xFFFFFFFFu, p, 20);
        const float pn2 = __shfl_sync(0xFFFFFFFFu, p, 24);
        const float pn3 = __shfl_sync(0xFFFFFFFFu, p, 28);

        const u64 vloC = pack2(vc.x, vc.y), vhiC = pack2(vc.z, vc.w);
        const u64 vloN = pack2(vn.x, vn.y), vhiN = pack2(vn.z, vn.w);

        aLo[0] = fma2(dup2(pn0), vloN, fma2(dup2(-pc0), vloC, aLo[0]));
        aHi[0] = fma2(dup2(pn0), vhiN, fma2(dup2(-pc0), vhiC, aHi[0]));
        aLo[1] = fma2(dup2(pn1), vloN, fma2(dup2(-pc1), vloC, aLo[1]));
        aHi[1] = fma2(dup2(pn1), vhiN, fma2(dup2(-pc1), vhiC, aHi[1]));
        aLo[2] = fma2(dup2(pn2), vloN, fma2(dup2(-pc2), vloC, aLo[2]));
        aHi[2] = fma2(dup2(pn2), vhiN, fma2(dup2(-pc2), vhiC, aHi[2]));
        aLo[3] = fma2(dup2(pn3), vloN, fma2(dup2(-pc3), vloC, aLo[3]));
        aHi[3] = fma2(dup2(pn3), vhiN, fma2(dup2(-pc3), vhiC, aHi[3]));
    }

    // ---- per-warp epilogue ----
    lsum += __shfl_xor_sync(0xFFFFFFFFu, lsum, 16);
    lsum += __shfl_xor_sync(0xFFFFFFFFu, lsum, 2);
    lsum += __shfl_xor_sync(0xFFFFFFFFu, lsum, 1);
    if (lane < 16 && (lane & 3) == 0)
        g_l[(t * HKV + w) * GQ + (lane >> 2)] = lsum * 0.25f;

    float4* og = (float4*)(g_o + ((size_t)(t * HKV + w) * GQ) * HD);
    #pragma unroll
    for (int g = 0; g < GQ; g++) {
        float x, y, z, ww;
        unpack2(aLo[g], x, y);
        unpack2(aHi[g], z, ww);
        og[g * 32 + lane] = make_float4(x, y, z, ww);
    }
}

// Combine NB block partials per (seq b, kv head kh).
// 512 threads: i4 = tid>>7 sums 4 partials each; smem tree combines.
__global__ void __launch_bounds__(512)
attn_reduce_kernel(float* __restrict__ out)
{
    const int b  = blockIdx.x;
    const int kh = blockIdx.y;
    const int q  = threadIdx.x & 127;   // (g, dq)
    const int g  = q >> 5;
    const int dq = q & 31;
    const int i4 = threadIdx.x >> 7;    // 0..3

    const int base = ((b * NBLK) * HKV + kh) * GQ + g;

    float4 acc = make_float4(0.f, 0.f, 0.f, 0.f);
    #pragma unroll
    for (int j = 0; j < 4; j++) {
        const int idx = base + (i4 * 4 + j) * HKV * GQ;
        float4 ov = ((const float4*)(g_o + (size_t)idx * HD))[dq];
        acc.x += ov.x; acc.y += ov.y; acc.z += ov.z; acc.w += ov.w;
    }

    __shared__ float4 sb[3][128];
    if (i4 > 0) sb[i4 - 1][q] = acc;
    __syncthreads();

    if (i4 == 0) {
        #pragma unroll
        for (int j = 0; j < 3; j++) {
            float4 ov = sb[j][q];
            acc.x += ov.x; acc.y += ov.y; acc.z += ov.z; acc.w += ov.w;
        }
        float L = 0.f;
        #pragma unroll
        for (int i = 0; i < NBLK; i++) L += g_l[base + i * HKV * GQ];
        const float inv = 1.0f / L;
        float4 r = make_float4(acc.x * inv, acc.y * inv, acc.z * inv, acc.w * inv);
        ((float4*)(out + ((size_t)b * NB_H + kh * GQ + g) * HD))[dq] = r;
    }
}

extern "C" void kernel_launch(void* const* d_in, const int* in_sizes, int n_in,
                              void* d_out, int out_size)
{
    const float* query         = (const float*)d_in[0];
    const float* knew          = (const float*)d_in[1];
    const float* vnew          = (const float*)d_in[2];
    const float* key_cache     = (const float*)d_in[3];
    const float* value_cache   = (const float*)d_in[4];
    const int*   block_list    = (const int*)d_in[5];
    const int*   block_groups  = (const int*)d_in[6];
    const int*   block_indices = (const int*)d_in[7];
    const int*   block_offsets = (const int*)d_in[8];
    const float* block_bias    = (const float*)d_in[9];
    float* out = (float*)d_out;

    attn_fused_kernel<<<TBLK, 256>>>(query, knew, vnew, key_cache, value_cache,
                                     block_list, block_groups, block_indices,
                                     block_offsets, block_bias);

    dim3 grid2(NB_B, HKV);
    attn_reduce_kernel<<<grid2, 512>>>(out);
}

// round 14
// speedup vs baseline: 1.0004x; 1.0004x over previous
#include <cuda_runtime.h>
#include <math_constants.h>

#define NB_B 32
#define NB_H 32
#define HKV 8
#define GQ 4
#define HD 128
#define BSZ 128
#define NBLK 16
#define TBLK (NB_B * NBLK)   // 512

__device__ float g_l[TBLK * HKV * GQ];
__device__ float g_o[TBLK * HKV * GQ * HD];

typedef unsigned long long u64;

__device__ __forceinline__ u64 pack2(float x, float y) {
    u64 r; asm("mov.b64 %0, {%1,%2};" : "=l"(r) : "f"(x), "f"(y)); return r;
}
__device__ __forceinline__ void unpack2(u64 v, float& x, float& y) {
    asm("mov.b64 {%0,%1}, %2;" : "=f"(x), "=f"(y) : "l"(v));
}
__device__ __forceinline__ u64 dup2(float x) {
    u64 r; asm("mov.b64 %0, {%1,%1};" : "=l"(r) : "f"(x)); return r;
}
__device__ __forceinline__ u64 fma2(u64 a, u64 b, u64 c) {
    u64 d; asm("fma.rn.f32x2 %0, %1, %2, %3;" : "=l"(d) : "l"(a), "l"(b), "l"(c)); return d;
}
__device__ __forceinline__ float dot4(float4 a, float4 b) {
    return fmaf(a.x, b.x, fmaf(a.y, b.y, fmaf(a.z, b.z, a.w * b.w)));
}

struct KV2 { float4 k0, v0, k1, v1; };

// Branch-free pair load straight from cache (new-token handled post-loop).
__device__ __forceinline__ KV2 load_pair(
    int s0, int nvalid, int lane, size_t rowstr,
    const float4* __restrict__ kbase, const float4* __restrict__ vbase)
{
    KV2 r;
    r.k0 = __ldcs(&kbase[(size_t)s0 * rowstr + lane]);
    r.v0 = __ldcs(&vbase[(size_t)s0 * rowstr + lane]);
    if (s0 + 1 < nvalid) {
        r.k1 = __ldcs(&kbase[(size_t)(s0 + 1) * rowstr + lane]);
        r.v1 = __ldcs(&vbase[(size_t)(s0 + 1) * rowstr + lane]);
    } else {
        r.k1 = make_float4(0.f, 0.f, 0.f, 0.f);
        r.v1 = make_float4(0.f, 0.f, 0.f, 0.f);
    }
    return r;
}

// One CTA per mapped block t; warp w owns kv head w. Software-pipelined.
__global__ void __launch_bounds__(256, 3)
attn_fused_kernel(const float* __restrict__ query,
                  const float* __restrict__ knew,
                  const float* __restrict__ vnew,
                  const float* __restrict__ kcache,
                  const float* __restrict__ vcache,
                  const int*   __restrict__ block_list,
                  const int*   __restrict__ block_groups,
                  const int*   __restrict__ block_indices,
                  const int*   __restrict__ block_offsets,
                  const float* __restrict__ bias)
{
    const int t    = blockIdx.x;
    const int tid  = threadIdx.x;
    const int lane = tid & 31;
    const int w    = tid >> 5;     // kv head

    __shared__ int s_sub;

    // Dead block: zero l (dead g_o entries are never read with nonzero weight).
    if (bias[t * BSZ] == -CUDART_INF_F) {
        if (tid < HKV * GQ) g_l[t * HKV * GQ + tid] = 0.0f;
        return;
    }

    const int grp = block_groups[t];
    const int cb  = block_list[t];

    if (tid == 0) {
        int sub = -1;
        #pragma unroll
        for (int b = 0; b < NB_B; b++) {
            if (block_indices[b] == cb) { sub = block_offsets[b] | (b << 16); break; }
        }
        s_sub = sub;
    }

    const int nvalid = __syncthreads_count(
        (tid < BSZ) && (bias[t * BSZ + tid] > -CUDART_INF_F));

    const int sub   = s_sub;
    const int sub_s = (sub < 0) ? -1 : (sub & 0xFFFF);
    const int sub_b = (sub < 0) ? 0  : (sub >> 16);

    const float SCL2 = 0.08838834764831845f * 1.4426950408889634f; // scale*log2e
    const float4* q4 = (const float4*)(query + ((size_t)grp * NB_H + w * GQ) * HD);
    float4 ql[GQ];
    #pragma unroll
    for (int g = 0; g < GQ; g++) {
        float4 qv = q4[g * (HD / 4) + lane];
        ql[g] = make_float4(qv.x * SCL2, qv.y * SCL2, qv.z * SCL2, qv.w * SCL2);
    }

    const size_t rowstr = (size_t)HKV * HD / 4;
    const float4* kbase = (const float4*)(kcache + ((size_t)cb * BSZ * HKV + w) * HD);
    const float4* vbase = (const float4*)(vcache + ((size_t)cb * BSZ * HKV + w) * HD);

    u64 aLo[GQ] = {0, 0, 0, 0}, aHi[GQ] = {0, 0, 0, 0};
    float lsum = 0.0f;
    const bool row_r = (lane & 16) != 0;
    const bool lo16  = !row_r;
    const bool hi8   = (lane & 8) != 0;
    const bool hi4   = (lane & 4) != 0;

    KV2 cur = load_pair(0, nvalid, lane, rowstr, kbase, vbase);

    for (int s0 = 0; s0 < nvalid; s0 += 2) {
        KV2 nxt;
        const int sn = s0 + 2;
        if (sn < nvalid)
            nxt = load_pair(sn, nvalid, lane, rowstr, kbase, vbase);

        const bool h1 = (s0 + 1 < nvalid);

        float v_[GQ], u_[GQ];
        #pragma unroll
        for (int g = 0; g < GQ; g++) {
            v_[g] = dot4(ql[g], cur.k0);
            u_[g] = dot4(ql[g], cur.k1);
        }

        float A[GQ];
        #pragma unroll
        for (int i = 0; i < GQ; i++) {
            float x  = lo16 ? u_[i] : v_[i];
            float rx = __shfl_xor_sync(0xFFFFFFFFu, x, 16);
            A[i] = (lo16 ? v_[i] : u_[i]) + rx;
        }
        float x0 = hi8 ? A[0] : A[2];
        float x1 = hi8 ? A[1] : A[3];
        float r0 = __shfl_xor_sync(0xFFFFFFFFu, x0, 8);
        float r1 = __shfl_xor_sync(0xFFFFFFFFu, x1, 8);
        float B0 = (hi8 ? A[2] : A[0]) + r0;
        float B1 = (hi8 ? A[3] : A[1]) + r1;
        float x2 = hi4 ? B0 : B1;
        float r2 = __shfl_xor_sync(0xFFFFFFFFu, x2, 4);
        float C  = (hi4 ? B1 : B0) + r2;
        C += __shfl_xor_sync(0xFFFFFFFFu, C, 2);
        C += __shfl_xor_sync(0xFFFFFFFFu, C, 1);
        if (row_r && !h1) C = -CUDART_INF_F;
        const float p = exp2f(C);
        lsum += p;

        const float p00 = __shfl_sync(0xFFFFFFFFu, p, 0);
        const float p01 = __shfl_sync(0xFFFFFFFFu, p, 4);
        const float p02 = __shfl_sync(0xFFFFFFFFu, p, 8);
        const float p03 = __shfl_sync(0xFFFFFFFFu, p, 12);
        const float p10 = __shfl_sync(0xFFFFFFFFu, p, 16);
        const float p11 = __shfl_sync(0xFFFFFFFFu, p, 20);
        const float p12 = __shfl_sync(0xFFFFFFFFu, p, 24);
        const float p13 = __shfl_sync(0xFFFFFFFFu, p, 28);

        const u64 vlo0 = pack2(cur.v0.x, cur.v0.y), vhi0 = pack2(cur.v0.z, cur.v0.w);
        const u64 vlo1 = pack2(cur.v1.x, cur.v1.y), vhi1 = pack2(cur.v1.z, cur.v1.w);

        aLo[0] = fma2(dup2(p00), vlo0, fma2(dup2(p10), vlo1, aLo[0]));
        aHi[0] = fma2(dup2(p00), vhi0, fma2(dup2(p10), vhi1, aHi[0]));
        aLo[1] = fma2(dup2(p01), vlo0, fma2(dup2(p11), vlo1, aLo[1]));
        aHi[1] = fma2(dup2(p01), vhi0, fma2(dup2(p11), vhi1, aHi[1]));
        aLo[2] = fma2(dup2(p02), vlo0, fma2(dup2(p12), vlo1, aLo[2]));
        aHi[2] = fma2(dup2(p02), vhi0, fma2(dup2(p12), vhi1, aHi[2]));
        aLo[3] = fma2(dup2(p03), vlo0, fma2(dup2(p13), vlo1, aLo[3]));
        aHi[3] = fma2(dup2(p03), vhi0, fma2(dup2(p13), vhi1, aHi[3]));

        cur = nxt;
    }

    // ---- new-token correction: subtract stale cache row, add new row ----
    if (sub_s >= 0) {
        const float4 kc = kbase[(size_t)sub_s * rowstr + lane];  // L1/L2 hot
        const float4 vc = vbase[(size_t)sub_s * rowstr + lane];
        const float4 kn = ((const float4*)(knew + ((size_t)sub_b * HKV + w) * HD))[lane];
        const float4 vn = ((const float4*)(vnew + ((size_t)sub_b * HKV + w) * HD))[lane];

        // fold with "row0 = stale cache row", "row1 = new row"
        float v_[GQ], u_[GQ];
        #pragma unroll
        for (int g = 0; g < GQ; g++) {
            v_[g] = dot4(ql[g], kc);
            u_[g] = dot4(ql[g], kn);
        }
        float A[GQ];
        #pragma unroll
        for (int i = 0; i < GQ; i++) {
            float x  = lo16 ? u_[i] : v_[i];
            float rx = __shfl_xor_sync(0xFFFFFFFFu, x, 16);
            A[i] = (lo16 ? v_[i] : u_[i]) + rx;
        }
        float x0 = hi8 ? A[0] : A[2];
        float x1 = hi8 ? A[1] : A[3];
        float r0 = __shfl_xor_sync(0xFFFFFFFFu, x0, 8);
        float r1 = __shfl_xor_sync(0xFFFFFFFFu, x1, 8);
        float B0 = (hi8 ? A[2] : A[0]) + r0;
        float B1 = (hi8 ? A[3] : A[1]) + r1;
        float x2 = hi4 ? B0 : B1;
        float r2 = __shfl_xor_sync(0xFFFFFFFFu, x2, 4);
        float C  = (hi4 ? B1 : B0) + r2;
        C += __shfl_xor_sync(0xFFFFFFFFu, C, 2);
        C += __shfl_xor_sync(0xFFFFFFFFu, C, 1);
        const float p = exp2f(C);
        lsum += row_r ? p : -p;   // + new, - stale

        const float pc0 = __shfl_sync(0xFFFFFFFFu, p, 0);
        const float pc1 = __shfl_sync(0xFFFFFFFFu, p, 4);
        const float pc2 = __shfl_sync(0xFFFFFFFFu, p, 8);
        const float pc3 = __shfl_sync(0xFFFFFFFFu, p, 12);
        const float pn0 = __shfl_sync(0xFFFFFFFFu, p, 16);
        const float pn1 = __shfl_sync(0xFFFFFFFFu, p, 20);
        const float pn2 = __shfl_sync(0xFFFFFFFFu, p, 24);
        const float pn3 = __shfl_sync(0xFFFFFFFFu, p, 28);

        const u64 vloC = pack2(vc.x, vc.y), vhiC = pack2(vc.z, vc.w);
        const u64 vloN = pack2(vn.x, vn.y), vhiN = pack2(vn.z, vn.w);

        aLo[0] = fma2(dup2(pn0), vloN, fma2(dup2(-pc0), vloC, aLo[0]));
        aHi[0] = fma2(dup2(pn0), vhiN, fma2(dup2(-pc0), vhiC, aHi[0]));
        aLo[1] = fma2(dup2(pn1), vloN, fma2(dup2(-pc1), vloC, aLo[1]));
        aHi[1] = fma2(dup2(pn1), vhiN, fma2(dup2(-pc1), vhiC, aHi[1]));
        aLo[2] = fma2(dup2(pn2), vloN, fma2(dup2(-pc2), vloC, aLo[2]));
        aHi[2] = fma2(dup2(pn2), vhiN, fma2(dup2(-pc2), vhiC, aHi[2]));
        aLo[3] = fma2(dup2(pn3), vloN, fma2(dup2(-pc3), vloC, aLo[3]));
        aHi[3] = fma2(dup2(pn3), vhiN, fma2(dup2(-pc3), vhiC, aHi[3]));
    }

    // ---- per-warp epilogue ----
    lsum += __shfl_xor_sync(0xFFFFFFFFu, lsum, 16);
    lsum += __shfl_xor_sync(0xFFFFFFFFu, lsum, 2);
    lsum += __shfl_xor_sync(0xFFFFFFFFu, lsum, 1);
    if (lane < 16 && (lane & 3) == 0)
        g_l[(t * HKV + w) * GQ + (lane >> 2)] = lsum * 0.25f;

    float4* og = (float4*)(g_o + ((size_t)(t * HKV + w) * GQ) * HD);
    #pragma unroll
    for (int g = 0; g < GQ; g++) {
        float x, y, z, ww;
        unpack2(aLo[g], x, y);
        unpack2(aHi[g], z, ww);
        og[g * 32 + lane] = make_float4(x, y, z, ww);
    }
}

// Combine NB block partials per (seq b, kv head kh).
// 512 threads: i4 = tid>>7 sums 4 partials each; smem tree combines.
__global__ void __launch_bounds__(512)
attn_reduce_kernel(float* __restrict__ out)
{
    const int b  = blockIdx.x;
    const int kh = blockIdx.y;
    const int q  = threadIdx.x & 127;   // (g, dq)
    const int g  = q >> 5;
    const int dq = q & 31;
    const int i4 = threadIdx.x >> 7;    // 0..3

    const int base = ((b * NBLK) * HKV + kh) * GQ + g;

    float4 acc = make_float4(0.f, 0.f, 0.f, 0.f);
    #pragma unroll
    for (int j = 0; j < 4; j++) {
        const int idx = base + (i4 * 4 + j) * HKV * GQ;
        float4 ov = ((const float4*)(g_o + (size_t)idx * HD))[dq];
        acc.x += ov.x; acc.y += ov.y; acc.z += ov.z; acc.w += ov.w;
    }

    __shared__ float4 sb[3][128];
    if (i4 > 0) sb[i4 - 1][q] = acc;
    __syncthreads();

    if (i4 == 0) {
        #pragma unroll
        for (int j = 0; j < 3; j++) {
            float4 ov = sb[j][q];
            acc.x += ov.x; acc.y += ov.y; acc.z += ov.z; acc.w += ov.w;
        }
        float L = 0.f;
        #pragma unroll
        for (int i = 0; i < NBLK; i++) L += g_l[base + i * HKV * GQ];
        const float inv = 1.0f / L;
        float4 r = make_float4(acc.x * inv, acc.y * inv, acc.z * inv, acc.w * inv);
        ((float4*)(out + ((size_t)b * NB_H + kh * GQ + g) * HD))[dq] = r;
    }
}

extern "C" void kernel_launch(void* const* d_in, const int* in_sizes, int n_in,
                              void* d_out, int out_size)
{
    const float* query         = (const float*)d_in[0];
    const float* knew          = (const float*)d_in[1];
    const float* vnew          = (const float*)d_in[2];
    const float* key_cache     = (const float*)d_in[3];
    const float* value_cache   = (const float*)d_in[4];
    const int*   block_list    = (const int*)d_in[5];
    const int*   block_groups  = (const int*)d_in[6];
    const int*   block_indices = (const int*)d_in[7];
    const int*   block_offsets = (const int*)d_in[8];
    const float* block_bias    = (const float*)d_in[9];
    float* out = (float*)d_out;

    attn_fused_kernel<<<TBLK, 256>>>(query, knew, vnew, key_cache, value_cache,
                                     block_list, block_groups, block_indices,
                                     block_offsets, block_bias);

    dim3 grid2(NB_B, HKV);
    attn_reduce_kernel<<<grid2, 512>>>(out);
}

// round 15
// speedup vs baseline: 1.0072x; 1.0068x over previous
#include <cuda_runtime.h>
#include <math_constants.h>

#define NB_B 32
#define NB_H 32
#define HKV 8
#define GQ 4
#define HD 128
#define BSZ 128
#define NBLK 16
#define TBLK (NB_B * NBLK)   // 512

__device__ float g_l[TBLK * HKV * GQ];
__device__ float g_o[TBLK * HKV * GQ * HD];

typedef unsigned long long u64;

__device__ __forceinline__ u64 pack2(float x, float y) {
    u64 r; asm("mov.b64 %0, {%1,%2};" : "=l"(r) : "f"(x), "f"(y)); return r;
}
__device__ __forceinline__ void unpack2(u64 v, float& x, float& y) {
    asm("mov.b64 {%0,%1}, %2;" : "=f"(x), "=f"(y) : "l"(v));
}
__device__ __forceinline__ u64 dup2(float x) {
    u64 r; asm("mov.b64 %0, {%1,%1};" : "=l"(r) : "f"(x)); return r;
}
__device__ __forceinline__ u64 fma2(u64 a, u64 b, u64 c) {
    u64 d; asm("fma.rn.f32x2 %0, %1, %2, %3;" : "=l"(d) : "l"(a), "l"(b), "l"(c)); return d;
}
__device__ __forceinline__ float dot4(float4 a, float4 b) {
    return fmaf(a.x, b.x, fmaf(a.y, b.y, fmaf(a.z, b.z, a.w * b.w)));
}

struct KV2 { float4 k0, v0, k1, v1; };

// Branch-free pair load straight from cache (new-token handled post-loop).
__device__ __forceinline__ KV2 load_pair(
    int s0, int nvalid, int lane, size_t rowstr,
    const float4* __restrict__ kbase, const float4* __restrict__ vbase)
{
    KV2 r;
    r.k0 = __ldcs(&kbase[(size_t)s0 * rowstr + lane]);
    r.v0 = __ldcs(&vbase[(size_t)s0 * rowstr + lane]);
    if (s0 + 1 < nvalid) {
        r.k1 = __ldcs(&kbase[(size_t)(s0 + 1) * rowstr + lane]);
        r.v1 = __ldcs(&vbase[(size_t)(s0 + 1) * rowstr + lane]);
    } else {
        r.k1 = make_float4(0.f, 0.f, 0.f, 0.f);
        r.v1 = make_float4(0.f, 0.f, 0.f, 0.f);
    }
    return r;
}

// One CTA per mapped block t; warp w owns kv head w. Software-pipelined.
__global__ void __launch_bounds__(256, 3)
attn_fused_kernel(const float* __restrict__ query,
                  const float* __restrict__ knew,
                  const float* __restrict__ vnew,
                  const float* __restrict__ kcache,
                  const float* __restrict__ vcache,
                  const int*   __restrict__ block_list,
                  const int*   __restrict__ block_groups,
                  const int*   __restrict__ block_indices,
                  const int*   __restrict__ block_offsets,
                  const float* __restrict__ bias)
{
    const int t    = blockIdx.x;
    const int tid  = threadIdx.x;
    const int lane = tid & 31;
    const int w    = tid >> 5;     // kv head

    __shared__ int s_sub;

    // Dead block: zero l (dead g_o entries are never read with nonzero weight).
    if (bias[t * BSZ] == -CUDART_INF_F) {
        if (tid < HKV * GQ) g_l[t * HKV * GQ + tid] = 0.0f;
        return;
    }

    const int grp = block_groups[t];
    const int cb  = block_list[t];

    if (tid == 0) {
        int sub = -1;
        #pragma unroll
        for (int b = 0; b < NB_B; b++) {
            if (block_indices[b] == cb) { sub = block_offsets[b] | (b << 16); break; }
        }
        s_sub = sub;
    }

    const int nvalid = __syncthreads_count(
        (tid < BSZ) && (bias[t * BSZ + tid] > -CUDART_INF_F));

    const int sub   = s_sub;
    const int sub_s = (sub < 0) ? -1 : (sub & 0xFFFF);
    const int sub_b = (sub < 0) ? 0  : (sub >> 16);

    const float SCL2 = 0.08838834764831845f * 1.4426950408889634f; // scale*log2e
    const float4* q4 = (const float4*)(query + ((size_t)grp * NB_H + w * GQ) * HD);
    float4 ql[GQ];
    #pragma unroll
    for (int g = 0; g < GQ; g++) {
        float4 qv = q4[g * (HD / 4) + lane];
        ql[g] = make_float4(qv.x * SCL2, qv.y * SCL2, qv.z * SCL2, qv.w * SCL2);
    }

    const size_t rowstr = (size_t)HKV * HD / 4;
    const float4* kbase = (const float4*)(kcache + ((size_t)cb * BSZ * HKV + w) * HD);
    const float4* vbase = (const float4*)(vcache + ((size_t)cb * BSZ * HKV + w) * HD);

    u64 aLo[GQ] = {0, 0, 0, 0}, aHi[GQ] = {0, 0, 0, 0};
    float lsum = 0.0f;
    const bool row_r = (lane & 16) != 0;
    const bool lo16  = !row_r;
    const bool hi8   = (lane & 8) != 0;
    const bool hi4   = (lane & 4) != 0;

    KV2 cur = load_pair(0, nvalid, lane, rowstr, kbase, vbase);

    for (int s0 = 0; s0 < nvalid; s0 += 2) {
        KV2 nxt;
        const int sn = s0 + 2;
        if (sn < nvalid)
            nxt = load_pair(sn, nvalid, lane, rowstr, kbase, vbase);

        const bool h1 = (s0 + 1 < nvalid);

        float v_[GQ], u_[GQ];
        #pragma unroll
        for (int g = 0; g < GQ; g++) {
            v_[g] = dot4(ql[g], cur.k0);
            u_[g] = dot4(ql[g], cur.k1);
        }

        float A[GQ];
        #pragma unroll
        for (int i = 0; i < GQ; i++) {
            float x  = lo16 ? u_[i] : v_[i];
            float rx = __shfl_xor_sync(0xFFFFFFFFu, x, 16);
            A[i] = (lo16 ? v_[i] : u_[i]) + rx;
        }
        float x0 = hi8 ? A[0] : A[2];
        float x1 = hi8 ? A[1] : A[3];
        float r0 = __shfl_xor_sync(0xFFFFFFFFu, x0, 8);
        float r1 = __shfl_xor_sync(0xFFFFFFFFu, x1, 8);
        float B0 = (hi8 ? A[2] : A[0]) + r0;
        float B1 = (hi8 ? A[3] : A[1]) + r1;
        float x2 = hi4 ? B0 : B1;
        float r2 = __shfl_xor_sync(0xFFFFFFFFu, x2, 4);
        float C  = (hi4 ? B1 : B0) + r2;
        C += __shfl_xor_sync(0xFFFFFFFFu, C, 2);
        C += __shfl_xor_sync(0xFFFFFFFFu, C, 1);
        if (row_r && !h1) C = -CUDART_INF_F;
        const float p = exp2f(C);
        lsum += p;

        const float p00 = __shfl_sync(0xFFFFFFFFu, p, 0);
        const float p01 = __shfl_sync(0xFFFFFFFFu, p, 4);
        const float p02 = __shfl_sync(0xFFFFFFFFu, p, 8);
        const float p03 = __shfl_sync(0xFFFFFFFFu, p, 12);
        const float p10 = __shfl_sync(0xFFFFFFFFu, p, 16);
        const float p11 = __shfl_sync(0xFFFFFFFFu, p, 20);
        const float p12 = __shfl_sync(0xFFFFFFFFu, p, 24);
        const float p13 = __shfl_sync(0xFFFFFFFFu, p, 28);

        const u64 vlo0 = pack2(cur.v0.x, cur.v0.y), vhi0 = pack2(cur.v0.z, cur.v0.w);
        const u64 vlo1 = pack2(cur.v1.x, cur.v1.y), vhi1 = pack2(cur.v1.z, cur.v1.w);

        aLo[0] = fma2(dup2(p00), vlo0, fma2(dup2(p10), vlo1, aLo[0]));
        aHi[0] = fma2(dup2(p00), vhi0, fma2(dup2(p10), vhi1, aHi[0]));
        aLo[1] = fma2(dup2(p01), vlo0, fma2(dup2(p11), vlo1, aLo[1]));
        aHi[1] = fma2(dup2(p01), vhi0, fma2(dup2(p11), vhi1, aHi[1]));
        aLo[2] = fma2(dup2(p02), vlo0, fma2(dup2(p12), vlo1, aLo[2]));
        aHi[2] = fma2(dup2(p02), vhi0, fma2(dup2(p12), vhi1, aHi[2]));
        aLo[3] = fma2(dup2(p03), vlo0, fma2(dup2(p13), vlo1, aLo[3]));
        aHi[3] = fma2(dup2(p03), vhi0, fma2(dup2(p13), vhi1, aHi[3]));

        cur = nxt;
    }

    // ---- new-token correction: subtract stale cache row, add new row ----
    if (sub_s >= 0) {
        const float4 kc = kbase[(size_t)sub_s * rowstr + lane];  // L1/L2 hot
        const float4 vc = vbase[(size_t)sub_s * rowstr + lane];
        const float4 kn = ((const float4*)(knew + ((size_t)sub_b * HKV + w) * HD))[lane];
        const float4 vn = ((const float4*)(vnew + ((size_t)sub_b * HKV + w) * HD))[lane];

        // fold with "row0 = stale cache row", "row1 = new row"
        float v_[GQ], u_[GQ];
        #pragma unroll
        for (int g = 0; g < GQ; g++) {
            v_[g] = dot4(ql[g], kc);
            u_[g] = dot4(ql[g], kn);
        }
        float A[GQ];
        #pragma unroll
        for (int i = 0; i < GQ; i++) {
            float x  = lo16 ? u_[i] : v_[i];
            float rx = __shfl_xor_sync(0xFFFFFFFFu, x, 16);
            A[i] = (lo16 ? v_[i] : u_[i]) + rx;
        }
        float x0 = hi8 ? A[0] : A[2];
        float x1 = hi8 ? A[1] : A[3];
        float r0 = __shfl_xor_sync(0xFFFFFFFFu, x0, 8);
        float r1 = __shfl_xor_sync(0xFFFFFFFFu, x1, 8);
        float B0 = (hi8 ? A[2] : A[0]) + r0;
        float B1 = (hi8 ? A[3] : A[1]) + r1;
        float x2 = hi4 ? B0 : B1;
        float r2 = __shfl_xor_sync(0xFFFFFFFFu, x2, 4);
        float C  = (hi4 ? B1 : B0) + r2;
        C += __shfl_xor_sync(0xFFFFFFFFu, C, 2);
        C += __shfl_xor_sync(0xFFFFFFFFu, C, 1);
        const float p = exp2f(C);
        lsum += row_r ? p : -p;   // + new, - stale

        const float pc0 = __shfl_sync(0xFFFFFFFFu, p, 0);
        const float pc1 = __shfl_sync(0xFFFFFFFFu, p, 4);
        const float pc2 = __shfl_sync(0xFFFFFFFFu, p, 8);
        const float pc3 = __shfl_sync(0xFFFFFFFFu, p, 12);
        const float pn0 = __shfl_sync(0xFFFFFFFFu, p, 16);
        const float pn1 = __shfl_sync(0xFFFFFFFFu, p, 20);
        const float pn2 = __shfl_sync(0xFFFFFFFFu, p, 24);
        const float pn3 = __shfl_sync(0xFFFFFFFFu, p, 28);

        const u64 vloC = pack2(vc.x, vc.y), vhiC = pack2(vc.z, vc.w);
        const u64 vloN = pack2(vn.x, vn.y), vhiN = pack2(vn.z, vn.w);

        aLo[0] = fma2(dup2(pn0), vloN, fma2(dup2(-pc0), vloC, aLo[0]));
        aHi[0] = fma2(dup2(pn0), vhiN, fma2(dup2(-pc0), vhiC, aHi[0]));
        aLo[1] = fma2(dup2(pn1), vloN, fma2(dup2(-pc1), vloC, aLo[1]));
        aHi[1] = fma2(dup2(pn1), vhiN, fma2(dup2(-pc1), vhiC, aHi[1]));
        aLo[2] = fma2(dup2(pn2), vloN, fma2(dup2(-pc2), vloC, aLo[2]));
        aHi[2] = fma2(dup2(pn2), vhiN, fma2(dup2(-pc2), vhiC, aHi[2]));
        aLo[3] = fma2(dup2(pn3), vloN, fma2(dup2(-pc3), vloC, aLo[3]));
        aHi[3] = fma2(dup2(pn3), vhiN, fma2(dup2(-pc3), vhiC, aHi[3]));
    }

    // ---- per-warp epilogue ----
    lsum += __shfl_xor_sync(0xFFFFFFFFu, lsum, 16);
    lsum += __shfl_xor_sync(0xFFFFFFFFu, lsum, 2);
    lsum += __shfl_xor_sync(0xFFFFFFFFu, lsum, 1);
    if (lane < 16 && (lane & 3) == 0)
        g_l[(t * HKV + w) * GQ + (lane >> 2)] = lsum * 0.25f;

    float4* og = (float4*)(g_o + ((size_t)(t * HKV + w) * GQ) * HD);
    #pragma unroll
    for (int g = 0; g < GQ; g++) {
        float x, y, z, ww;
        unpack2(aLo[g], x, y);
        unpack2(aHi[g], z, ww);
        og[g * 32 + lane] = make_float4(x, y, z, ww);
    }
}

// Combine NB block partials per (seq b, kv head kh).
// 512 threads: i4 = tid>>7 sums 4 partials each; smem tree combines.
__global__ void __launch_bounds__(512)
attn_reduce_kernel(float* __restrict__ out)
{
    const int b  = blockIdx.x;
    const int kh = blockIdx.y;
    const int q  = threadIdx.x & 127;   // (g, dq)
    const int g  = q >> 5;
    const int dq = q & 31;
    const int i4 = threadIdx.x >> 7;    // 0..3

    const int base = ((b * NBLK) * HKV + kh) * GQ + g;

    float4 acc = make_float4(0.f, 0.f, 0.f, 0.f);
    #pragma unroll
    for (int j = 0; j < 4; j++) {
        const int idx = base + (i4 * 4 + j) * HKV * GQ;
        float4 ov = ((const float4*)(g_o + (size_t)idx * HD))[dq];
        acc.x += ov.x; acc.y += ov.y; acc.z += ov.z; acc.w += ov.w;
    }

    __shared__ float4 sb[3][128];
    if (i4 > 0) sb[i4 - 1][q] = acc;
    __syncthreads();

    if (i4 == 0) {
        #pragma unroll
        for (int j = 0; j < 3; j++) {
            float4 ov = sb[j][q];
            acc.x += ov.x; acc.y += ov.y; acc.z += ov.z; acc.w += ov.w;
        }
        float L = 0.f;
        #pragma unroll
        for (int i = 0; i < NBLK; i++) L += g_l[base + i * HKV * GQ];
        const float inv = 1.0f / L;
        float4 r = make_float4(acc.x * inv, acc.y * inv, acc.z * inv, acc.w * inv);
        ((float4*)(out + ((size_t)b * NB_H + kh * GQ + g) * HD))[dq] = r;
    }
}

extern "C" void kernel_launch(void* const* d_in, const int* in_sizes, int n_in,
                              void* d_out, int out_size)
{
    const float* query         = (const float*)d_in[0];
    const float* knew          = (const float*)d_in[1];
    const float* vnew          = (const float*)d_in[2];
    const float* key_cache     = (const float*)d_in[3];
    const float* value_cache   = (const float*)d_in[4];
    const int*   block_list    = (const int*)d_in[5];
    const int*   block_groups  = (const int*)d_in[6];
    const int*   block_indices = (const int*)d_in[7];
    const int*   block_offsets = (const int*)d_in[8];
    const float* block_bias    = (const float*)d_in[9];
    float* out = (float*)d_out;

    attn_fused_kernel<<<TBLK, 256>>>(query, knew, vnew, key_cache, value_cache,
                                     block_list, block_groups, block_indices,
                                     block_offsets, block_bias);

    dim3 grid2(NB_B, HKV);
    attn_reduce_kernel<<<grid2, 512>>>(out);
}